// round 2
// baseline (speedup 1.0000x reference)
#include <cuda_runtime.h>
#include <cstdint>
#include <cstddef>

// out = (G @ W @ A) @ depthwise_conv3x3(x)
//   A = softmax(attention_weights, axis=1), G = softmax(global_attention_weight, axis=1)
//   W = pointwise_weights[:, :, 0, 0]
// x: [8, 64, 256, 256] f32; out same shape.

#define NCH 64
#define IMG 256
#define TH 8
#define TW 16
#define HALO_H 10
#define HALO_W 18
#define XS_CS 181          // channel stride (floats) in xs smem, odd for bank spread
#define DWS_S 136          // pixel-row stride of dw tile; 136 % 32 == 8 -> conflict-free B frags
#define SMEM_FLOATS (NCH * XS_CS + 576 + NCH * DWS_S)   // 11584 + 576 + 8704 = 20864
#define SMEM_BYTES (SMEM_FLOATS * 4)                    // 83456 B -> 2 CTAs/SM

__device__ float g_M[NCH * NCH];   // fused mixing matrix M = G @ W @ A

// ---------------------------------------------------------------------------
// helpers
// ---------------------------------------------------------------------------
__device__ __forceinline__ unsigned f2tf(float x) {
    unsigned r;
    asm("cvt.rna.tf32.f32 %0, %1;" : "=r"(r) : "f"(x));
    return r;
}

__device__ __forceinline__ void mma_tf32(float d[4], const unsigned a[4],
                                         unsigned b0, unsigned b1) {
    asm volatile(
        "mma.sync.aligned.m16n8k8.row.col.f32.tf32.tf32.f32 "
        "{%0,%1,%2,%3}, {%4,%5,%6,%7}, {%8,%9}, {%0,%1,%2,%3};\n"
        : "+f"(d[0]), "+f"(d[1]), "+f"(d[2]), "+f"(d[3])
        : "r"(a[0]), "r"(a[1]), "r"(a[2]), "r"(a[3]), "r"(b0), "r"(b1));
}

// ---------------------------------------------------------------------------
// Kernel 1: M = softmax(G) @ W @ softmax(A)   (one CTA, 256 threads; tiny)
// ---------------------------------------------------------------------------
__global__ void compute_M_kernel(const float* __restrict__ aw,
                                 const float* __restrict__ gw,
                                 const float* __restrict__ pw) {
    __shared__ float As[NCH * NCH];
    __shared__ float Gs[NCH * NCH];
    __shared__ float Ts[NCH * NCH];
    float* red = Ts;  // reuse Ts as the reduction scratch during softmax phases

    const int t = threadIdx.x;       // 256 threads
    const int r = t >> 2, s = t & 3; // 4 threads per row

    // ---- softmax rows of aw -> As ----
    {
        const float* row = aw + r * NCH;
        float mx = -3.4e38f;
        for (int j = s; j < NCH; j += 4) mx = fmaxf(mx, row[j]);
        red[r * 4 + s] = mx;
        __syncthreads();
        mx = fmaxf(fmaxf(red[r * 4 + 0], red[r * 4 + 1]),
                   fmaxf(red[r * 4 + 2], red[r * 4 + 3]));
        __syncthreads();
        float sum = 0.f;
        for (int j = s; j < NCH; j += 4) {
            float e = __expf(row[j] - mx);
            As[r * NCH + j] = e;
            sum += e;
        }
        red[r * 4 + s] = sum;
        __syncthreads();
        sum = red[r * 4 + 0] + red[r * 4 + 1] + red[r * 4 + 2] + red[r * 4 + 3];
        float inv = 1.f / sum;
        for (int j = s; j < NCH; j += 4) As[r * NCH + j] *= inv;
        __syncthreads();
    }
    // ---- softmax rows of gw -> Gs ----
    {
        const float* row = gw + r * NCH;
        float mx = -3.4e38f;
        for (int j = s; j < NCH; j += 4) mx = fmaxf(mx, row[j]);
        red[r * 4 + s] = mx;
        __syncthreads();
        mx = fmaxf(fmaxf(red[r * 4 + 0], red[r * 4 + 1]),
                   fmaxf(red[r * 4 + 2], red[r * 4 + 3]));
        __syncthreads();
        float sum = 0.f;
        for (int j = s; j < NCH; j += 4) {
            float e = __expf(row[j] - mx);
            Gs[r * NCH + j] = e;
            sum += e;
        }
        red[r * 4 + s] = sum;
        __syncthreads();
        sum = red[r * 4 + 0] + red[r * 4 + 1] + red[r * 4 + 2] + red[r * 4 + 3];
        float inv = 1.f / sum;
        for (int j = s; j < NCH; j += 4) Gs[r * NCH + j] *= inv;
        __syncthreads();
    }
    // ---- Ts = W @ As ----  (overwrites the red scratch; synced above)
    float tloc[16];
    for (int ii = 0; ii < 16; ii++) {
        int e = t + ii * 256;
        int i = e >> 6, c = e & 63;
        float acc = 0.f;
        #pragma unroll 8
        for (int j = 0; j < NCH; j++)
            acc = fmaf(__ldg(pw + i * NCH + j), As[j * NCH + c], acc);
        tloc[ii] = acc;
    }
    __syncthreads();
    for (int ii = 0; ii < 16; ii++) Ts[t + ii * 256] = tloc[ii];
    __syncthreads();
    // ---- g_M = Gs @ Ts ----
    for (int e = t; e < NCH * NCH; e += 256) {
        int k = e >> 6, c = e & 63;
        float acc = 0.f;
        #pragma unroll 8
        for (int j = 0; j < NCH; j++)
            acc = fmaf(Gs[k * NCH + j], Ts[j * NCH + c], acc);
        g_M[e] = acc;
    }
}

// ---------------------------------------------------------------------------
// Kernel 2: fused depthwise-conv + channel mix
//   grid (16, 32, 8), block 256.  Tile: 8x16 pixels, all 64 channels.
// ---------------------------------------------------------------------------
extern __shared__ float smem[];

__global__ void __launch_bounds__(256, 2)
fused_kernel(const float* __restrict__ x, const float* __restrict__ dwwt,
             float* __restrict__ out) {
    float* xs  = smem;                  // [64][10*18] with channel stride 181
    float* wts = xs + NCH * XS_CS;      // [64][9]
    float* dws = wts + 576;             // [64][128] with row stride 136

    const int t    = threadIdx.x;
    const int b    = blockIdx.z;
    const int ty   = blockIdx.y, tx = blockIdx.x;
    const int y0   = ty * TH - 1, x0 = tx * TW - 1;

    const int wid  = t >> 5, lane = t & 31;
    const int warpM = wid & 3;       // 4 groups of 16 out-channels
    const int warpN = wid >> 2;      // 2 groups of 64 pixels
    const int g = lane >> 2, m = lane & 3;

    // ---- A fragments: M[warpM*16 .. +16][0..64) held in registers (L2-served) ----
    unsigned afr[8][4];
    {
        const int r0 = warpM * 16 + g;
        #pragma unroll
        for (int ks = 0; ks < 8; ks++) {
            int col = ks * 8 + m;
            afr[ks][0] = f2tf(__ldg(g_M + r0 * NCH + col));
            afr[ks][1] = f2tf(__ldg(g_M + (r0 + 8) * NCH + col));
            afr[ks][2] = f2tf(__ldg(g_M + r0 * NCH + col + 4));
            afr[ks][3] = f2tf(__ldg(g_M + (r0 + 8) * NCH + col + 4));
        }
    }

    // ---- stage x halo tile + depthwise weights ----
    const float* xb = x + ((size_t)b * NCH) * (IMG * IMG);
    for (int idx = t; idx < NCH * HALO_H * HALO_W; idx += 256) {
        int c   = idx / (HALO_H * HALO_W);
        int rem = idx - c * (HALO_H * HALO_W);
        int ry  = rem / HALO_W;
        int rx  = rem - ry * HALO_W;
        int gy = y0 + ry, gx = x0 + rx;
        float v = 0.f;
        if ((unsigned)gy < (unsigned)IMG && (unsigned)gx < (unsigned)IMG)
            v = __ldg(xb + c * (IMG * IMG) + gy * IMG + gx);
        xs[c * XS_CS + ry * HALO_W + rx] = v;
    }
    for (int idx = t; idx < 576; idx += 256) wts[idx] = __ldg(dwwt + idx);
    __syncthreads();

    // ---- depthwise 3x3 conv (fp32 exact), rolling 3-column window ----
    {
        const int c = t >> 2, q = t & 3;   // thread owns 1 channel, 2 rows x 16 px
        const float* xc = xs + c * XS_CS;
        float wr[9];
        #pragma unroll
        for (int k = 0; k < 9; k++) wr[k] = wts[c * 9 + k];
        #pragma unroll
        for (int rr = 0; rr < 2; rr++) {
            const int oy = q * 2 + rr;
            const float* bp = xc + oy * HALO_W;
            float* drow = dws + c * DWS_S + oy * TW;
            float a0 = bp[0], a1 = bp[HALO_W],     a2 = bp[2 * HALO_W];
            float b0 = bp[1], b1 = bp[1 + HALO_W], b2 = bp[1 + 2 * HALO_W];
            #pragma unroll
            for (int ox = 0; ox < TW; ox++) {
                float c0 = bp[ox + 2];
                float c1 = bp[ox + 2 + HALO_W];
                float c2 = bp[ox + 2 + 2 * HALO_W];
                float acc =          a0 * wr[0];
                acc = fmaf(a1, wr[3], acc);
                acc = fmaf(a2, wr[6], acc);
                acc = fmaf(b0, wr[1], acc);
                acc = fmaf(b1, wr[4], acc);
                acc = fmaf(b2, wr[7], acc);
                acc = fmaf(c0, wr[2], acc);
                acc = fmaf(c1, wr[5], acc);
                acc = fmaf(c2, wr[8], acc);
                drow[ox] = acc;
                a0 = b0; a1 = b1; a2 = b2;
                b0 = c0; b1 = c1; b2 = c2;
            }
        }
    }
    __syncthreads();

    // ---- channel mix: out[64,128] = M @ dw  via m16n8k8 tf32 MMA ----
    const size_t outBase = ((size_t)b * NCH) * (IMG * IMG)
                         + (size_t)(ty * TH) * IMG + tx * TW;
    #pragma unroll
    for (int pair = 0; pair < 4; pair++) {
        const int pb0 = warpN * 64 + pair * 16;   // two n-chunks: pb0, pb0+8
        float acc0[4] = {0.f, 0.f, 0.f, 0.f};
        float acc1[4] = {0.f, 0.f, 0.f, 0.f};
        #pragma unroll
        for (int ks = 0; ks < 8; ks++) {
            const float* bp = dws + (ks * 8 + m) * DWS_S;
            unsigned b0a = f2tf(bp[pb0 + g]);
            unsigned b1a = f2tf(bp[4 * DWS_S + pb0 + g]);
            unsigned b0b = f2tf(bp[pb0 + 8 + g]);
            unsigned b1b = f2tf(bp[4 * DWS_S + pb0 + 8 + g]);
            mma_tf32(acc0, afr[ks], b0a, b1a);
            mma_tf32(acc1, afr[ks], b0b, b1b);
        }
        const int och = warpM * 16 + g;
        const int p0 = pb0 + 2 * m;
        const int p1 = pb0 + 8 + 2 * m;

        {
            size_t off = outBase + (size_t)och * (IMG * IMG) + (p0 >> 4) * IMG + (p0 & 15);
            *reinterpret_cast<float2*>(out + off) = make_float2(acc0[0], acc0[1]);
        }
        {
            size_t off = outBase + (size_t)(och + 8) * (IMG * IMG) + (p0 >> 4) * IMG + (p0 & 15);
            *reinterpret_cast<float2*>(out + off) = make_float2(acc0[2], acc0[3]);
        }
        {
            size_t off = outBase + (size_t)och * (IMG * IMG) + (p1 >> 4) * IMG + (p1 & 15);
            *reinterpret_cast<float2*>(out + off) = make_float2(acc1[0], acc1[1]);
        }
        {
            size_t off = outBase + (size_t)(och + 8) * (IMG * IMG) + (p1 >> 4) * IMG + (p1 & 15);
            *reinterpret_cast<float2*>(out + off) = make_float2(acc1[2], acc1[3]);
        }
    }
}

// ---------------------------------------------------------------------------
extern "C" void kernel_launch(void* const* d_in, const int* in_sizes, int n_in,
                              void* d_out, int out_size) {
    const float* x   = (const float*)d_in[0];   // [8,64,256,256]
    const float* dww = (const float*)d_in[1];   // [64,1,3,3]
    const float* pww = (const float*)d_in[2];   // [64,64,1,1]
    const float* aw  = (const float*)d_in[3];   // [64,64]
    const float* gw  = (const float*)d_in[4];   // [64,64]
    float* out = (float*)d_out;

    compute_M_kernel<<<1, 256>>>(aw, gw, pww);

    cudaFuncSetAttribute(fused_kernel,
                         cudaFuncAttributeMaxDynamicSharedMemorySize, SMEM_BYTES);
    dim3 grid(IMG / TW, IMG / TH, 8);
    fused_kernel<<<grid, 256, SMEM_BYTES>>>(x, dww, out);
}